// round 2
// baseline (speedup 1.0000x reference)
#include <cuda_runtime.h>
#include <cuda_bf16.h>

#define R_TOT   16384      // H*W rays
#define KPRIM   32
#define NSTEPS  64
#define DTSTEP  (1.0f/64.0f)

// Scratch: template transposed to float4 (r,g,b,a per voxel), 32 prims * 4096 voxels
__device__ float4 g_templ4[KPRIM * 4096];

// --- Prologue: transpose template [K,4,16,16,16] -> [K, 4096] float4 ---
__global__ void transpose_tmpl_kernel(const float* __restrict__ tmpl) {
    int idx = blockIdx.x * blockDim.x + threadIdx.x;
    if (idx >= KPRIM * 4096) return;
    int k = idx >> 12;
    int v = idx & 4095;
    const float* b = tmpl + (size_t)k * 4 * 4096;
    g_templ4[idx] = make_float4(b[v], b[4096 + v], b[8192 + v], b[12288 + v]);
}

// --- Main march: one warp per ray, one lane per primitive ---
__global__ void __launch_bounds__(256) march_kernel(
    const float* __restrict__ raypos,
    const float* __restrict__ raydir,
    const float* __restrict__ tminmax,
    const float* __restrict__ primpos,
    const float* __restrict__ primrot,
    const float* __restrict__ primscale,
    float* __restrict__ out)
{
    int gtid = blockIdx.x * blockDim.x + threadIdx.x;
    int ray  = gtid >> 5;
    int lane = threadIdx.x & 31;
    if (ray >= R_TOT) return;

    // Per-lane primitive parameters (registers)
    float ppx = primpos[lane * 3 + 0];
    float ppy = primpos[lane * 3 + 1];
    float ppz = primpos[lane * 3 + 2];
    float r00 = primrot[lane * 9 + 0], r01 = primrot[lane * 9 + 1], r02 = primrot[lane * 9 + 2];
    float r10 = primrot[lane * 9 + 3], r11 = primrot[lane * 9 + 4], r12 = primrot[lane * 9 + 5];
    float r20 = primrot[lane * 9 + 6], r21 = primrot[lane * 9 + 7], r22 = primrot[lane * 9 + 8];
    float s0 = primscale[lane * 3 + 0];
    float s1 = primscale[lane * 3 + 1];
    float s2 = primscale[lane * 3 + 2];

    // Per-ray data (redundant loads across warp; L1-broadcast)
    float rpx = raypos[ray * 3 + 0];
    float rpy = raypos[ray * 3 + 1];
    float rpz = raypos[ray * 3 + 2];
    float rdx = raydir[ray * 3 + 0];
    float rdy = raydir[ray * 3 + 1];
    float rdz = raydir[ray * 3 + 2];
    float tmin = tminmax[ray * 2 + 0];
    float tmax = tminmax[ray * 2 + 1];

    const float4* __restrict__ T = g_templ4 + lane * 4096;

    float rgbx = 0.f, rgby = 0.f, rgbz = 0.f, alpha = 0.f;

    #pragma unroll 1
    for (int i = 0; i < NSTEPS; i++) {
        float t  = tmin + (float)i * DTSTEP;
        float px = fmaf(rdx, t, rpx);
        float py = fmaf(rdy, t, rpy);
        float pz = fmaf(rdz, t, rpz);

        float xlx = px - ppx, xly = py - ppy, xlz = pz - ppz;
        float y0 = (r00 * xlx + r01 * xly + r02 * xlz) * s0;
        float y1 = (r10 * xlx + r11 * xly + r12 * xlz) * s1;
        float y2 = (r20 * xlx + r21 * xly + r22 * xlz) * s2;

        float sx = 0.f, sy = 0.f, sz = 0.f, sw = 0.f;
        if (fabsf(y0) <= 1.0f && fabsf(y1) <= 1.0f && fabsf(y2) <= 1.0f) {
            // trilinear: component 0 -> z index, 1 -> y, 2 -> x
            float gz = (y0 + 1.0f) * 0.5f * 15.0f;
            float gy = (y1 + 1.0f) * 0.5f * 15.0f;
            float gx = (y2 + 1.0f) * 0.5f * 15.0f;
            int iz = min(max((int)floorf(gz), 0), 14);
            int iy = min(max((int)floorf(gy), 0), 14);
            int ix = min(max((int)floorf(gx), 0), 14);
            float fz = fminf(fmaxf(gz - (float)iz, 0.f), 1.f);
            float fy = fminf(fmaxf(gy - (float)iy, 0.f), 1.f);
            float fx = fminf(fmaxf(gx - (float)ix, 0.f), 1.f);

            int base = iz * 256 + iy * 16 + ix;
            float4 c000 = __ldg(T + base);
            float4 c001 = __ldg(T + base + 1);
            float4 c010 = __ldg(T + base + 16);
            float4 c011 = __ldg(T + base + 17);
            float4 c100 = __ldg(T + base + 256);
            float4 c101 = __ldg(T + base + 257);
            float4 c110 = __ldg(T + base + 272);
            float4 c111 = __ldg(T + base + 273);

            // lerp x
            float a00x = c000.x + fx * (c001.x - c000.x);
            float a00y = c000.y + fx * (c001.y - c000.y);
            float a00z = c000.z + fx * (c001.z - c000.z);
            float a00w = c000.w + fx * (c001.w - c000.w);
            float a01x = c010.x + fx * (c011.x - c010.x);
            float a01y = c010.y + fx * (c011.y - c010.y);
            float a01z = c010.z + fx * (c011.z - c010.z);
            float a01w = c010.w + fx * (c011.w - c010.w);
            float a10x = c100.x + fx * (c101.x - c100.x);
            float a10y = c100.y + fx * (c101.y - c100.y);
            float a10z = c100.z + fx * (c101.z - c100.z);
            float a10w = c100.w + fx * (c101.w - c100.w);
            float a11x = c110.x + fx * (c111.x - c110.x);
            float a11y = c110.y + fx * (c111.y - c110.y);
            float a11z = c110.z + fx * (c111.z - c110.z);
            float a11w = c110.w + fx * (c111.w - c110.w);
            // lerp y
            float b0x = a00x + fy * (a01x - a00x);
            float b0y = a00y + fy * (a01y - a00y);
            float b0z = a00z + fy * (a01z - a00z);
            float b0w = a00w + fy * (a01w - a00w);
            float b1x = a10x + fy * (a11x - a10x);
            float b1y = a10y + fy * (a11y - a10y);
            float b1z = a10z + fy * (a11z - a10z);
            float b1w = a10w + fy * (a11w - a10w);
            // lerp z
            sx = b0x + fz * (b1x - b0x);
            sy = b0y + fz * (b1y - b0y);
            sz = b0z + fz * (b1z - b0z);
            sw = b0w + fz * (b1w - b0w);
        }

        // Warp-sum over 32 primitives
        #pragma unroll
        for (int off = 16; off; off >>= 1) {
            sx += __shfl_xor_sync(0xffffffffu, sx, off);
            sy += __shfl_xor_sync(0xffffffffu, sy, off);
            sz += __shfl_xor_sync(0xffffffffu, sz, off);
            sw += __shfl_xor_sync(0xffffffffu, sw, off);
        }

        float valid = (t < tmax) ? 1.0f : 0.0f;
        float na = fminf(fmaxf(alpha + sw * DTSTEP * valid, 0.0f), 1.0f);
        float contrib = na - alpha;
        rgbx = fmaf(sx, contrib, rgbx);
        rgby = fmaf(sy, contrib, rgby);
        rgbz = fmaf(sz, contrib, rgbz);
        alpha = na;
    }

    if (lane == 0) {
        // out layout: rayrgb [1,3,H,W] | rayalpha [1,1,H,W] | rayrgba [1,4,H,W]
        out[0 * R_TOT + ray] = rgbx;
        out[1 * R_TOT + ray] = rgby;
        out[2 * R_TOT + ray] = rgbz;
        out[3 * R_TOT + ray] = alpha;
        out[4 * R_TOT + ray] = rgbx;
        out[5 * R_TOT + ray] = rgby;
        out[6 * R_TOT + ray] = rgbz;
        out[7 * R_TOT + ray] = alpha;
    }
}

extern "C" void kernel_launch(void* const* d_in, const int* in_sizes, int n_in,
                              void* d_out, int out_size) {
    const float* raypos    = (const float*)d_in[0];
    const float* raydir    = (const float*)d_in[1];
    const float* tminmax   = (const float*)d_in[2];
    const float* primpos   = (const float*)d_in[3];
    const float* primrot   = (const float*)d_in[4];
    const float* primscale = (const float*)d_in[5];
    const float* tmpl      = (const float*)d_in[6];
    float* out = (float*)d_out;

    transpose_tmpl_kernel<<<(KPRIM * 4096 + 255) / 256, 256>>>(tmpl);

    int threads = R_TOT * 32;
    march_kernel<<<threads / 256, 256>>>(raypos, raydir, tminmax,
                                         primpos, primrot, primscale, out);
}

// round 3
// speedup vs baseline: 10.5935x; 10.5935x over previous
#include <cuda_runtime.h>
#include <cuda_fp16.h>

#define R_TOT   16384      // H*W rays
#define KPRIM   32
#define NSTEPS  64
#define DTSTEP  (1.0f/64.0f)

// Packed template: per (k,z,y,x): {half2 r(x,x+1), half2 g(x,x+1), half2 b(x,x+1), half2 a(x,x+1)} = 16B
__device__ uint4 g_tpair[KPRIM * 4096];   // 2 MB, L2-resident

// --- Prologue: pack template [K,4,16,16,16] fp32 -> fp16 corner pairs ---
__global__ void pack_tmpl_kernel(const float* __restrict__ tmpl) {
    int idx = blockIdx.x * blockDim.x + threadIdx.x;
    if (idx >= KPRIM * 4096) return;
    int k = idx >> 12;
    int v = idx & 4095;            // z*256 + y*16 + x
    int x = v & 15;
    int x1 = (x < 15) ? 1 : 0;     // clamp x+1
    const float* b = tmpl + (size_t)k * 4 * 4096;
    __half2 hr = __floats2half2_rn(b[v],           b[v + x1]);
    __half2 hg = __floats2half2_rn(b[4096 + v],    b[4096 + v + x1]);
    __half2 hb = __floats2half2_rn(b[8192 + v],    b[8192 + v + x1]);
    __half2 ha = __floats2half2_rn(b[12288 + v],   b[12288 + v + x1]);
    uint4 q;
    q.x = *(unsigned int*)&hr;
    q.y = *(unsigned int*)&hg;
    q.z = *(unsigned int*)&hb;
    q.w = *(unsigned int*)&ha;
    g_tpair[idx] = q;
}

__device__ __forceinline__ float4 xlerp4(uint4 q, float fx) {
    float2 r = __half22float2(*(__half2*)&q.x);
    float2 g = __half22float2(*(__half2*)&q.y);
    float2 b = __half22float2(*(__half2*)&q.z);
    float2 a = __half22float2(*(__half2*)&q.w);
    return make_float4(fmaf(fx, r.y - r.x, r.x),
                       fmaf(fx, g.y - g.x, g.x),
                       fmaf(fx, b.y - b.x, b.x),
                       fmaf(fx, a.y - a.x, a.x));
}

// --- Main march: one warp per ray, one lane per primitive ---
__global__ void __launch_bounds__(256) march_kernel(
    const float* __restrict__ raypos,
    const float* __restrict__ raydir,
    const float* __restrict__ tminmax,
    const float* __restrict__ primpos,
    const float* __restrict__ primrot,
    const float* __restrict__ primscale,
    float* __restrict__ out)
{
    int gtid = blockIdx.x * blockDim.x + threadIdx.x;
    int ray  = gtid >> 5;
    int lane = threadIdx.x & 31;
    if (ray >= R_TOT) return;

    // Per-lane primitive parameters (registers)
    float ppx = primpos[lane * 3 + 0];
    float ppy = primpos[lane * 3 + 1];
    float ppz = primpos[lane * 3 + 2];
    float r00 = primrot[lane * 9 + 0], r01 = primrot[lane * 9 + 1], r02 = primrot[lane * 9 + 2];
    float r10 = primrot[lane * 9 + 3], r11 = primrot[lane * 9 + 4], r12 = primrot[lane * 9 + 5];
    float r20 = primrot[lane * 9 + 6], r21 = primrot[lane * 9 + 7], r22 = primrot[lane * 9 + 8];
    float s0 = primscale[lane * 3 + 0];
    float s1 = primscale[lane * 3 + 1];
    float s2 = primscale[lane * 3 + 2];

    float rpx = raypos[ray * 3 + 0];
    float rpy = raypos[ray * 3 + 1];
    float rpz = raypos[ray * 3 + 2];
    float rdx = raydir[ray * 3 + 0];
    float rdy = raydir[ray * 3 + 1];
    float rdz = raydir[ray * 3 + 2];
    float tmin = tminmax[ray * 2 + 0];
    float tmax = tminmax[ray * 2 + 1];

    const uint4* __restrict__ T = g_tpair + lane * 4096;

    float rgbx = 0.f, rgby = 0.f, rgbz = 0.f, alpha = 0.f;

    #pragma unroll 1
    for (int i = 0; i < NSTEPS; i++) {
        float t = fmaf((float)i, DTSTEP, tmin);
        if (t >= tmax) break;               // warp-uniform: all later steps contribute 0

        float px = fmaf(rdx, t, rpx);
        float py = fmaf(rdy, t, rpy);
        float pz = fmaf(rdz, t, rpz);

        float xlx = px - ppx, xly = py - ppy, xlz = pz - ppz;
        float y0 = (r00 * xlx + r01 * xly + r02 * xlz) * s0;
        float y1 = (r10 * xlx + r11 * xly + r12 * xlz) * s1;
        float y2 = (r20 * xlx + r21 * xly + r22 * xlz) * s2;

        float sx = 0.f, sy = 0.f, sz = 0.f, sw = 0.f;
        if (fabsf(y0) <= 1.0f && fabsf(y1) <= 1.0f && fabsf(y2) <= 1.0f) {
            // component 0 -> z index, 1 -> y, 2 -> x
            float gz = (y0 + 1.0f) * 0.5f * 15.0f;
            float gy = (y1 + 1.0f) * 0.5f * 15.0f;
            float gx = (y2 + 1.0f) * 0.5f * 15.0f;
            int iz = min(max((int)floorf(gz), 0), 14);
            int iy = min(max((int)floorf(gy), 0), 14);
            int ix = min(max((int)floorf(gx), 0), 14);
            float fz = fminf(fmaxf(gz - (float)iz, 0.f), 1.f);
            float fy = fminf(fmaxf(gy - (float)iy, 0.f), 1.f);
            float fx = fminf(fmaxf(gx - (float)ix, 0.f), 1.f);

            int base = iz * 256 + iy * 16 + ix;
            uint4 q00 = __ldg(T + base);            // (iz,  iy)
            uint4 q01 = __ldg(T + base + 16);       // (iz,  iy+1)
            uint4 q10 = __ldg(T + base + 256);      // (iz+1,iy)
            uint4 q11 = __ldg(T + base + 272);      // (iz+1,iy+1)

            float4 a00 = xlerp4(q00, fx);
            float4 a01 = xlerp4(q01, fx);
            float4 a10 = xlerp4(q10, fx);
            float4 a11 = xlerp4(q11, fx);

            float b0x = fmaf(fy, a01.x - a00.x, a00.x);
            float b0y = fmaf(fy, a01.y - a00.y, a00.y);
            float b0z = fmaf(fy, a01.z - a00.z, a00.z);
            float b0w = fmaf(fy, a01.w - a00.w, a00.w);
            float b1x = fmaf(fy, a11.x - a10.x, a10.x);
            float b1y = fmaf(fy, a11.y - a10.y, a10.y);
            float b1z = fmaf(fy, a11.z - a10.z, a10.z);
            float b1w = fmaf(fy, a11.w - a10.w, a10.w);

            sx = fmaf(fz, b1x - b0x, b0x);
            sy = fmaf(fz, b1y - b0y, b0y);
            sz = fmaf(fz, b1z - b0z, b0z);
            sw = fmaf(fz, b1w - b0w, b0w);
        }

        // Warp-sum of alpha channel only (butterfly -> all lanes hold the sum)
        #pragma unroll
        for (int off = 16; off; off >>= 1)
            sw += __shfl_xor_sync(0xffffffffu, sw, off);

        float na = fminf(fmaxf(fmaf(sw, DTSTEP, alpha), 0.0f), 1.0f);
        float contrib = na - alpha;         // warp-uniform
        rgbx = fmaf(sx, contrib, rgbx);     // per-lane partial; reduced at the end
        rgby = fmaf(sy, contrib, rgby);
        rgbz = fmaf(sz, contrib, rgbz);
        alpha = na;
        if (alpha >= 1.0f) break;           // saturated: contrib stays 0
    }

    // Final rgb reduction across the warp
    #pragma unroll
    for (int off = 16; off; off >>= 1) {
        rgbx += __shfl_xor_sync(0xffffffffu, rgbx, off);
        rgby += __shfl_xor_sync(0xffffffffu, rgby, off);
        rgbz += __shfl_xor_sync(0xffffffffu, rgbz, off);
    }

    if (lane == 0) {
        // out layout: rayrgb [1,3,H,W] | rayalpha [1,1,H,W] | rayrgba [1,4,H,W]
        out[0 * R_TOT + ray] = rgbx;
        out[1 * R_TOT + ray] = rgby;
        out[2 * R_TOT + ray] = rgbz;
        out[3 * R_TOT + ray] = alpha;
        out[4 * R_TOT + ray] = rgbx;
        out[5 * R_TOT + ray] = rgby;
        out[6 * R_TOT + ray] = rgbz;
        out[7 * R_TOT + ray] = alpha;
    }
}

extern "C" void kernel_launch(void* const* d_in, const int* in_sizes, int n_in,
                              void* d_out, int out_size) {
    const float* raypos    = (const float*)d_in[0];
    const float* raydir    = (const float*)d_in[1];
    const float* tminmax   = (const float*)d_in[2];
    const float* primpos   = (const float*)d_in[3];
    const float* primrot   = (const float*)d_in[4];
    const float* primscale = (const float*)d_in[5];
    const float* tmpl      = (const float*)d_in[6];
    float* out = (float*)d_out;

    pack_tmpl_kernel<<<(KPRIM * 4096 + 255) / 256, 256>>>(tmpl);

    int threads = R_TOT * 32;
    march_kernel<<<threads / 256, 256>>>(raypos, raydir, tminmax,
                                         primpos, primrot, primscale, out);
}